// round 16
// baseline (speedup 1.0000x reference)
#include <cuda_runtime.h>
#include <cuda_fp16.h>
#include <cstdint>

// Problem constants
#define BATCH   4
#define S_LEN   2048
#define HID     1024
#define NH      16
#define HD      64
#define M_TOTAL (BATCH * S_LEN)   // 8192
#define NBH     (BATCH * NH)      // 64

#define LOG2E 1.4426950408889634f

// fp16 scratch
__device__ __half g_Xh[(size_t)M_TOTAL * HID];
__device__ __half g_Wh[3][(size_t)HID * HID];
__device__ __half g_Qh[(size_t)NBH * S_LEN * HD];     // Q*0.125*log2e+bq'
__device__ __half g_Kh[(size_t)NBH * S_LEN * HD];
__device__ __half g_Vh[(size_t)NBH * S_LEN * HD];

// ===========================================================================
// helpers
// ===========================================================================
__device__ __forceinline__ uint32_t smem_u32(const void* p) {
    uint32_t a;
    asm("{ .reg .u64 t; cvta.to.shared.u64 t, %1; cvt.u32.u64 %0, t; }"
        : "=r"(a) : "l"(p));
    return a;
}

__device__ __forceinline__ void cpa16(uint32_t s, const void* g) {
    asm volatile("cp.async.cg.shared.global [%0], [%1], 16;" :: "r"(s), "l"(g));
}
#define CP_COMMIT() asm volatile("cp.async.commit_group;" ::: "memory")
#define CP_WAIT(n)  asm volatile("cp.async.wait_group %0;" :: "n"(n) : "memory")

// fp32-accum fp16 mma (GEMM + PV)
__device__ __forceinline__ void mma16(float* c, const uint32_t* a,
                                      uint32_t b0, uint32_t b1) {
    asm volatile(
        "mma.sync.aligned.m16n8k16.row.col.f32.f16.f16.f32 "
        "{%0,%1,%2,%3}, {%4,%5,%6,%7}, {%8,%9}, {%0,%1,%2,%3};"
        : "+f"(c[0]), "+f"(c[1]), "+f"(c[2]), "+f"(c[3])
        : "r"(a[0]), "r"(a[1]), "r"(a[2]), "r"(a[3]), "r"(b0), "r"(b1));
}

// fp16-accum fp16 mma (QK^T scores): 2x rate on the legacy tensor pipe.
__device__ __forceinline__ void mma16h(uint32_t* c, const uint32_t* a,
                                       uint32_t b0, uint32_t b1) {
    asm volatile(
        "mma.sync.aligned.m16n8k16.row.col.f16.f16.f16.f16 "
        "{%0,%1}, {%2,%3,%4,%5}, {%6,%7}, {%0,%1};"
        : "+r"(c[0]), "+r"(c[1])
        : "r"(a[0]), "r"(a[1]), "r"(a[2]), "r"(a[3]), "r"(b0), "r"(b1));
}

__device__ __forceinline__ void ldsm_x4(uint32_t* r, uint32_t a) {
    asm volatile("ldmatrix.sync.aligned.m8n8.x4.shared.b16 {%0,%1,%2,%3}, [%4];"
        : "=r"(r[0]), "=r"(r[1]), "=r"(r[2]), "=r"(r[3]) : "r"(a));
}
__device__ __forceinline__ void ldsm_x4t(uint32_t* r, uint32_t a) {
    asm volatile("ldmatrix.sync.aligned.m8n8.x4.trans.shared.b16 {%0,%1,%2,%3}, [%4];"
        : "=r"(r[0]), "=r"(r[1]), "=r"(r[2]), "=r"(r[3]) : "r"(a));
}

__device__ __forceinline__ uint32_t h2u(__half2 h) {
    return *reinterpret_cast<uint32_t*>(&h);
}
__device__ __forceinline__ __half2 u2h(uint32_t u) {
    return *reinterpret_cast<__half2*>(&u);
}

__device__ __forceinline__ __half2 ex2h2(__half2 x) {
    __half2 r;
    asm("ex2.approx.f16x2 %0, %1;"
        : "=r"(*(uint32_t*)&r) : "r"(*(const uint32_t*)&x));
    return r;
}

// ===========================================================================
// Prepass: fp32 -> fp16, 8 floats/thread, one 16B store (full sectors)
// ===========================================================================
#define XN ((size_t)M_TOTAL * HID)
#define WN ((size_t)HID * HID)
#define CVT_BLOCKS ((int)((XN + 3 * WN) / 2048))

__global__ __launch_bounds__(256) void cvt_all(
    const float* __restrict__ X,  const float* __restrict__ Wq,
    const float* __restrict__ Wk, const float* __restrict__ Wv,
    __half* __restrict__ xh, __half* __restrict__ wh)
{
    size_t i = ((size_t)blockIdx.x * 256 + threadIdx.x) * 8;
    const float* src;
    __half* dst;
    if (i < XN) {
        src = X + i;  dst = xh + i;
    } else {
        size_t r = i - XN;
        int w = (int)(r / WN);
        size_t o = r - (size_t)w * WN;
        src = (w == 0 ? Wq : w == 1 ? Wk : Wv) + o;
        dst = wh + (size_t)w * WN + o;
    }
    float4 v0 = *(const float4*)src;
    float4 v1 = *(const float4*)(src + 4);
    __half2 h[4];
    h[0] = __floats2half2_rn(v0.x, v0.y);
    h[1] = __floats2half2_rn(v0.z, v0.w);
    h[2] = __floats2half2_rn(v1.x, v1.y);
    h[3] = __floats2half2_rn(v1.z, v1.w);
    *(uint4*)dst = *(const uint4*)h;
}

// ===========================================================================
// Kernel 1: fused QKV GEMM (R15/R13 config, unchanged).  4 warps, warp tile
// 64x64, CTA 128x128, BK=64, 2-stage cp.async, 2 CTAs/SM.
// ===========================================================================
#define GROW 144
#define GSTB (128 * GROW)
#define GEMM_SMEM_BYTES (4 * GSTB)        // 73728
#define CROW 136

__global__ __launch_bounds__(128, 2) void qkv_gemm_h(
    const float* __restrict__ bq, const float* __restrict__ bk,
    const float* __restrict__ bv)
{
    extern __shared__ __half sh[];
    const uint32_t sbase = smem_u32(sh);

    const int tid  = threadIdx.x;
    const int lane = tid & 31;
    const int wid  = tid >> 5;            // 0..3
    const int grp  = lane >> 2;
    const int qid  = lane & 3;
    const int wm   = (wid >> 1) * 64;
    const int wn   = (wid & 1) * 64;

    const int z  = blockIdx.z;
    const __half* X = g_Xh;
    const __half* W = g_Wh[z];
    const float* bias = (z == 0) ? bq : (z == 1) ? bk : bv;
    __half* out = (z == 0) ? g_Qh : (z == 1) ? g_Kh : g_Vh;
    const float scale = (z == 0) ? (0.125f * LOG2E) : 1.0f;

    const int m0 = blockIdx.y * 128;
    const int n0 = blockIdx.x * 128;

    const int lr = tid >> 3;              // 0..15, +16*rep
    const int lc = tid & 7;

    float acc[4][8][4];
    #pragma unroll
    for (int i = 0; i < 4; i++)
        #pragma unroll
        for (int j = 0; j < 8; j++)
            #pragma unroll
            for (int r = 0; r < 4; r++) acc[i][j][r] = 0.f;

    #define LOAD_STAGE(st, kb) do {                                           \
        _Pragma("unroll")                                                     \
        for (int rep = 0; rep < 8; rep++) {                                   \
            int r = lr + rep * 16;                                            \
            cpa16(sbase + (st) * GSTB + r * GROW + lc * 16,                   \
                  X + (size_t)(m0 + r) * HID + (kb) + lc * 8);                \
        }                                                                     \
        _Pragma("unroll")                                                     \
        for (int rep = 0; rep < 8; rep++) {                                   \
            int r = lr + rep * 16;                                            \
            cpa16(sbase + 2 * GSTB + (st) * GSTB + r * GROW + lc * 16,        \
                  W + (size_t)(n0 + r) * HID + (kb) + lc * 8);                \
        }                                                                     \
    } while (0)

    LOAD_STAGE(0, 0);
    CP_COMMIT();

    const uint32_t aoff = (wm + (lane & 15)) * GROW + (lane >> 4) * 16;
    const uint32_t boff = (wn + (lane & 7)) * GROW + (lane >> 3) * 16;

    for (int it = 0; it < HID / 64; it++) {
        CP_WAIT(0);
        __syncthreads();

        if (it + 1 < HID / 64) {
            LOAD_STAGE((it + 1) & 1, (it + 1) * 64);
            CP_COMMIT();
        }

        const int st = it & 1;
        const uint32_t Ab = sbase + st * GSTB + aoff;
        const uint32_t Bb = sbase + 2 * GSTB + st * GSTB + boff;

        #pragma unroll
        for (int s2 = 0; s2 < 2; s2++) {
            uint32_t bf[8][4];
            #pragma unroll
            for (int j = 0; j < 8; j++)
                ldsm_x4(bf[j], Bb + j * 8 * GROW + s2 * 64);
            #pragma unroll
            for (int s = 0; s < 2; s++) {
                uint32_t af[4][4];
                #pragma unroll
                for (int i = 0; i < 4; i++)
                    ldsm_x4(af[i], Ab + i * 16 * GROW + s2 * 64 + s * 32);
                #pragma unroll
                for (int j = 0; j < 8; j++)
                    #pragma unroll
                    for (int i = 0; i < 4; i++)
                        mma16(acc[i][j], af[i], bf[j][s * 2], bf[j][s * 2 + 1]);
            }
        }
    }

    // ---- epilogue: bias+scale -> C smem -> coalesced 128B stores ----
    float2 bias2[8];
    #pragma unroll
    for (int j = 0; j < 8; j++)
        bias2[j] = *(const float2*)&bias[n0 + wn + j * 8 + 2 * qid];

    __syncthreads();
    #pragma unroll
    for (int i = 0; i < 4; i++) {
        const int r0 = wm + i * 16 + grp;
        #pragma unroll
        for (int j = 0; j < 8; j++) {
            const int cc = wn + j * 8 + 2 * qid;
            *(__half2*)&sh[r0 * CROW + cc] = __floats2half2_rn(
                (acc[i][j][0] + bias2[j].x) * scale,
                (acc[i][j][1] + bias2[j].y) * scale);
            *(__half2*)&sh[(r0 + 8) * CROW + cc] = __floats2half2_rn(
                (acc[i][j][2] + bias2[j].x) * scale,
                (acc[i][j][3] + bias2[j].y) * scale);
        }
    }
    __syncthreads();

    #pragma unroll
    for (int p = 0; p < 16; p++) {
        const int u     = tid + p * 128;
        const int chunk = u & 7;
        const int half_ = (u >> 3) & 1;
        const int row   = u >> 4;
        const int m  = m0 + row;
        const int b_ = m >> 11;
        const int s  = m & 2047;
        const int h  = (n0 >> 6) + half_;
        uint4 v = *(const uint4*)&sh[row * CROW + half_ * 64 + chunk * 8];
        *(uint4*)&out[((size_t)(b_ * NH + h) * S_LEN + s) * HD + chunk * 8] = v;
    }
    #undef LOAD_STAGE
}

// ===========================================================================
// Kernel 2: flash attention.  4 warps x 32 q-rows, 64-key tiles.
// QK^T fp16-accum, PV fp32-accum, fixed-shift softmax, mask pre-folded,
// staged coalesced output.
// NEW: 3-stage K/V ring -> ONE __syncthreads per tile (prefetch targets a
// buffer whose readers are already past this iteration's sync).
// ===========================================================================
#define AROW 144
#define ATILE (64 * AROW)                 // 9216 B
#define ABUF (2 * ATILE)                  // K + V per stage: 18432 B
#define NSTG 3
#define MSK_OFF_H ((NSTG * ABUF) / 2)     // half-index of mask buffer: 27648
#define ATT_SMEM_BYTES (NSTG * ABUF + 4096)   // 59392

__global__ __launch_bounds__(128, 2) void attention_h(
    const float* __restrict__ mask, float* __restrict__ out)
{
    extern __shared__ __half sh[];
    const uint32_t sbase = smem_u32(sh);

    const int tid  = threadIdx.x;
    const int lane = tid & 31;
    const int wid  = tid >> 5;            // 0..3
    const int grp  = lane >> 2;
    const int qid  = lane & 3;
    const int qb   = wid * 32;

    const int qt = blockIdx.x;            // 0..15
    const int bh = blockIdx.y;            // 0..63
    const int b_ = bh >> 4;
    const int h  = bh & 15;
    const int q0 = qt * 128;

    const __half* Kbh = g_Kh + (size_t)bh * S_LEN * HD;
    const __half* Vbh = g_Vh + (size_t)bh * S_LEN * HD;
    const float* mrow = mask + (size_t)b_ * S_LEN;

    // ---- pre-fold mask into smem: mh[k] = half(mask[k]*log2e - 4) ----
    for (int u = tid; u < 512; u += 128) {
        float4 mv = *(const float4*)&mrow[u * 4];
        *(__half2*)&sh[MSK_OFF_H + u * 4] =
            __floats2half2_rn(fmaf(mv.x, LOG2E, -4.f), fmaf(mv.y, LOG2E, -4.f));
        *(__half2*)&sh[MSK_OFF_H + u * 4 + 2] =
            __floats2half2_rn(fmaf(mv.z, LOG2E, -4.f), fmaf(mv.w, LOG2E, -4.f));
    }

    // ---- Q fragments (2 row-tiles of 16), register-resident ----
    uint32_t qf[2][4][4];
    {
        const __half* qp = g_Qh + ((size_t)bh * S_LEN + q0 + qb + grp) * HD + 2 * qid;
        #pragma unroll
        for (int i = 0; i < 2; i++) {
            const __half* qpi = qp + (size_t)i * 16 * HD;
            #pragma unroll
            for (int ks = 0; ks < 4; ks++) {
                qf[i][ks][0] = *(const uint32_t*)(qpi + ks * 16);
                qf[i][ks][1] = *(const uint32_t*)(qpi + 8 * HD + ks * 16);
                qf[i][ks][2] = *(const uint32_t*)(qpi + ks * 16 + 8);
                qf[i][ks][3] = *(const uint32_t*)(qpi + 8 * HD + ks * 16 + 8);
            }
        }
    }

    float o[2][8][4];
    #pragma unroll
    for (int i = 0; i < 2; i++)
        #pragma unroll
        for (int j = 0; j < 8; j++)
            #pragma unroll
            for (int r = 0; r < 4; r++) o[i][j][r] = 0.f;
    float l_[2][2] = {{0.f, 0.f}, {0.f, 0.f}};

    #define LOAD_TILE(buf, t) do {                                            \
        const int k0t_ = (t) * 64;                                            \
        _Pragma("unroll")                                                     \
        for (int rep = 0; rep < 8; rep++) {                                   \
            int u = tid + rep * 128;                                          \
            int tn = u >> 9, rr = (u >> 3) & 63, cc = u & 7;                  \
            const __half* g = tn                                              \
                ? (Vbh + (size_t)(k0t_ + rr) * HD + cc * 8)                   \
                : (Kbh + (size_t)(k0t_ + rr) * HD + cc * 8);                  \
            cpa16(sbase + (buf) * ABUF + tn * ATILE + rr * AROW + cc * 16, g);\
        }                                                                     \
    } while (0)

    LOAD_TILE(0, 0);  CP_COMMIT();
    LOAD_TILE(1, 1);  CP_COMMIT();

    const uint32_t koff = (lane & 7) * AROW + (lane >> 3) * 16;       // x4
    const uint32_t voff = (lane & 15) * AROW + (lane >> 4) * 16;      // x4t

    for (int t = 0; t < S_LEN / 64; t++) {
        CP_WAIT(1);         // tile t landed; tile t+1 may stay in flight
        __syncthreads();    // all warps past iter t-1 compute; tile t visible

        // prefetch t+2 into buffer (t+2)%3 == (t-1)%3 — its readers are done
        if (t + 2 < S_LEN / 64) LOAD_TILE((t + 2) % NSTG, t + 2);
        CP_COMMIT();        // unconditional: fixed group accounting

        const uint32_t Ksb = sbase + (t % NSTG) * ABUF;
        const uint32_t Vsb = Ksb + ATILE;

        // ---- S' = Q' K^T  (log2 domain), fp16 accumulators ----
        uint32_t sacc[2][8][2];
        #pragma unroll
        for (int i = 0; i < 2; i++)
            #pragma unroll
            for (int j = 0; j < 8; j++) {
                sacc[i][j][0] = 0u;
                sacc[i][j][1] = 0u;
            }

        #pragma unroll
        for (int j = 0; j < 8; j++) {
            const uint32_t ka = Ksb + j * 8 * AROW + koff;
            uint32_t kb[4];
            ldsm_x4(kb, ka);               // ks 0,1
            mma16h(sacc[0][j], qf[0][0], kb[0], kb[1]);
            mma16h(sacc[0][j], qf[0][1], kb[2], kb[3]);
            mma16h(sacc[1][j], qf[1][0], kb[0], kb[1]);
            mma16h(sacc[1][j], qf[1][1], kb[2], kb[3]);
            ldsm_x4(kb, ka + 64);          // ks 2,3
            mma16h(sacc[0][j], qf[0][2], kb[0], kb[1]);
            mma16h(sacc[0][j], qf[0][3], kb[2], kb[3]);
            mma16h(sacc[1][j], qf[1][2], kb[0], kb[1]);
            mma16h(sacc[1][j], qf[1][3], kb[2], kb[3]);
        }

        // ---- fixed-shift softmax: p = 2^(s' + mh) — all half2 ----
        const int k0t = t * 64;
        uint32_t pf[2][4][4];
        __half2 ps0[2], ps1[2];
        ps0[0] = ps0[1] = ps1[0] = ps1[1] = __float2half2_rn(0.f);
        #pragma unroll
        for (int j = 0; j < 8; j++) {
            const __half2 mh =
                *(const __half2*)&sh[MSK_OFF_H + k0t + j * 8 + 2 * qid];
            #pragma unroll
            for (int i = 0; i < 2; i++) {
                __half2 e0 = ex2h2(__hadd2(u2h(sacc[i][j][0]), mh));  // rows g
                __half2 e1 = ex2h2(__hadd2(u2h(sacc[i][j][1]), mh));  // rows g+8
                ps0[i] = __hadd2(ps0[i], e0);
                ps1[i] = __hadd2(ps1[i], e1);
                pf[i][j >> 1][(j & 1) * 2 + 0] = h2u(e0);
                pf[i][j >> 1][(j & 1) * 2 + 1] = h2u(e1);
            }
        }
        #pragma unroll
        for (int i = 0; i < 2; i++) {      // per-tile promote to fp32
            float2 f0 = __half22float2(ps0[i]);
            float2 f1 = __half22float2(ps1[i]);
            l_[i][0] += f0.x + f0.y;
            l_[i][1] += f1.x + f1.y;
        }

        // ---- O += P V  (fp32 accum) ----
        #pragma unroll
        for (int jp = 0; jp < 8; jp += 2) {
            #pragma unroll
            for (int ks = 0; ks < 4; ks++) {
                uint32_t vb[4];
                ldsm_x4t(vb, Vsb + ks * 16 * AROW + jp * 16 + voff);
                mma16(o[0][jp],     pf[0][ks], vb[0], vb[1]);
                mma16(o[0][jp + 1], pf[0][ks], vb[2], vb[3]);
                mma16(o[1][jp],     pf[1][ks], vb[0], vb[1]);
                mma16(o[1][jp + 1], pf[1][ks], vb[2], vb[3]);
            }
        }
        // no end-of-loop sync: next iter's post-wait sync covers buffer reuse
    }
    #undef LOAD_TILE

    // ---- final l reduction across the 4 qid lanes ----
    #pragma unroll
    for (int i = 0; i < 2; i++)
        #pragma unroll
        for (int g2 = 0; g2 < 2; g2++)
            #pragma unroll
            for (int off = 1; off < 4; off <<= 1)
                l_[i][g2] += __shfl_xor_sync(0xFFFFFFFF, l_[i][g2], off);

    // ---- normalize -> stage C in smem (row stride 72 f32) -> coalesced ----
    float* cs = (float*)sh;               // K/V buffers are dead now
    __syncthreads();                      // all warps done with smem tiles
    #pragma unroll
    for (int i = 0; i < 2; i++) {
        const float i0 = 1.0f / l_[i][0];
        const float i1 = 1.0f / l_[i][1];
        const int r0 = qb + i * 16 + grp;
        #pragma unroll
        for (int j = 0; j < 8; j++) {
            const int dd = j * 8 + 2 * qid;
            *(float2*)&cs[r0 * 72 + dd] =
                make_float2(o[i][j][0] * i0, o[i][j][1] * i0);
            *(float2*)&cs[(r0 + 8) * 72 + dd] =
                make_float2(o[i][j][2] * i1, o[i][j][3] * i1);
        }
    }
    __syncthreads();

    #pragma unroll
    for (int p = 0; p < 16; p++) {
        const int u   = tid + p * 128;
        const int c4  = u & 15;            // 16 float4 per 64-float row
        const int row = u >> 4;            // 0..127
        const int s   = q0 + row;
        float4 v = *(const float4*)&cs[row * 72 + c4 * 4];
        *(float4*)&out[((size_t)(b_ * S_LEN + s)) * HID + h * HD + c4 * 4] = v;
    }
}

// ===========================================================================
extern "C" void kernel_launch(void* const* d_in, const int* in_sizes, int n_in,
                              void* d_out, int out_size)
{
    const float* X    = (const float*)d_in[0];
    const float* mask = (const float*)d_in[1];
    const float* Wq   = (const float*)d_in[2];
    const float* bq   = (const float*)d_in[3];
    const float* Wk   = (const float*)d_in[4];
    const float* bk   = (const float*)d_in[5];
    const float* Wv   = (const float*)d_in[6];
    const float* bv   = (const float*)d_in[7];
    float* out = (float*)d_out;

    cudaFuncSetAttribute(qkv_gemm_h,
        cudaFuncAttributeMaxDynamicSharedMemorySize, GEMM_SMEM_BYTES);
    cudaFuncSetAttribute(attention_h,
        cudaFuncAttributeMaxDynamicSharedMemorySize, ATT_SMEM_BYTES);

    __half* xh;  cudaGetSymbolAddress((void**)&xh, g_Xh);
    __half* wh;  cudaGetSymbolAddress((void**)&wh, g_Wh);

    // prepass: fp32 -> fp16
    cvt_all<<<CVT_BLOCKS, 256>>>(X, Wq, Wk, Wv, xh, wh);

    // QKV projection (R13/R15 config)
    dim3 g1(HID / 128, M_TOTAL / 128, 3);   // (8, 64, 3)
    qkv_gemm_h<<<g1, 128, GEMM_SMEM_BYTES>>>(bq, bk, bv);

    // attention
    dim3 g2(S_LEN / 128, NBH);              // (16, 64)
    attention_h<<<g2, 128, ATT_SMEM_BYTES>>>(mask, out);
}

// round 17
// speedup vs baseline: 1.5272x; 1.5272x over previous
#include <cuda_runtime.h>
#include <cuda_fp16.h>
#include <cstdint>

// Problem constants
#define BATCH   4
#define S_LEN   2048
#define HID     1024
#define NH      16
#define HD      64
#define M_TOTAL (BATCH * S_LEN)   // 8192
#define NBH     (BATCH * NH)      // 64

#define LOG2E 1.4426950408889634f

// fp16 scratch
__device__ __half g_Xh[(size_t)M_TOTAL * HID];
__device__ __half g_Wh[3][(size_t)HID * HID];
__device__ __half g_Qh[(size_t)NBH * S_LEN * HD];     // Q*0.125*log2e+bq'
__device__ __half g_Kh[(size_t)NBH * S_LEN * HD];
__device__ __half g_Vh[(size_t)NBH * S_LEN * HD];

// ===========================================================================
// helpers
// ===========================================================================
__device__ __forceinline__ uint32_t smem_u32(const void* p) {
    uint32_t a;
    asm("{ .reg .u64 t; cvta.to.shared.u64 t, %1; cvt.u32.u64 %0, t; }"
        : "=r"(a) : "l"(p));
    return a;
}

__device__ __forceinline__ void cpa16(uint32_t s, const void* g) {
    asm volatile("cp.async.cg.shared.global [%0], [%1], 16;" :: "r"(s), "l"(g));
}
#define CP_COMMIT() asm volatile("cp.async.commit_group;" ::: "memory")
#define CP_WAIT(n)  asm volatile("cp.async.wait_group %0;" :: "n"(n) : "memory")

// fp32-accum fp16 mma (GEMM + PV)
__device__ __forceinline__ void mma16(float* c, const uint32_t* a,
                                      uint32_t b0, uint32_t b1) {
    asm volatile(
        "mma.sync.aligned.m16n8k16.row.col.f32.f16.f16.f32 "
        "{%0,%1,%2,%3}, {%4,%5,%6,%7}, {%8,%9}, {%0,%1,%2,%3};"
        : "+f"(c[0]), "+f"(c[1]), "+f"(c[2]), "+f"(c[3])
        : "r"(a[0]), "r"(a[1]), "r"(a[2]), "r"(a[3]), "r"(b0), "r"(b1));
}

// fp16-accum fp16 mma (QK^T scores): 2x rate on the legacy tensor pipe.
__device__ __forceinline__ void mma16h(uint32_t* c, const uint32_t* a,
                                       uint32_t b0, uint32_t b1) {
    asm volatile(
        "mma.sync.aligned.m16n8k16.row.col.f16.f16.f16.f16 "
        "{%0,%1}, {%2,%3,%4,%5}, {%6,%7}, {%0,%1};"
        : "+r"(c[0]), "+r"(c[1])
        : "r"(a[0]), "r"(a[1]), "r"(a[2]), "r"(a[3]), "r"(b0), "r"(b1));
}

__device__ __forceinline__ void ldsm_x4(uint32_t* r, uint32_t a) {
    asm volatile("ldmatrix.sync.aligned.m8n8.x4.shared.b16 {%0,%1,%2,%3}, [%4];"
        : "=r"(r[0]), "=r"(r[1]), "=r"(r[2]), "=r"(r[3]) : "r"(a));
}
__device__ __forceinline__ void ldsm_x4t(uint32_t* r, uint32_t a) {
    asm volatile("ldmatrix.sync.aligned.m8n8.x4.trans.shared.b16 {%0,%1,%2,%3}, [%4];"
        : "=r"(r[0]), "=r"(r[1]), "=r"(r[2]), "=r"(r[3]) : "r"(a));
}

__device__ __forceinline__ uint32_t h2u(__half2 h) {
    return *reinterpret_cast<uint32_t*>(&h);
}
__device__ __forceinline__ __half2 u2h(uint32_t u) {
    return *reinterpret_cast<__half2*>(&u);
}

__device__ __forceinline__ __half2 ex2h2(__half2 x) {
    __half2 r;
    asm("ex2.approx.f16x2 %0, %1;"
        : "=r"(*(uint32_t*)&r) : "r"(*(const uint32_t*)&x));
    return r;
}

// ===========================================================================
// Prepass: fp32 -> fp16 (single launch)  [R15 version]
// ===========================================================================
#define XN ((size_t)M_TOTAL * HID)
#define WN ((size_t)HID * HID)
#define CVT_BLOCKS ((int)((XN + 3 * WN) / 1024))

__global__ __launch_bounds__(256) void cvt_all(
    const float* __restrict__ X,  const float* __restrict__ Wq,
    const float* __restrict__ Wk, const float* __restrict__ Wv,
    __half* __restrict__ xh, __half* __restrict__ wh)
{
    size_t i = ((size_t)blockIdx.x * 256 + threadIdx.x) * 4;
    const float* src;
    __half* dst;
    if (i < XN) {
        src = X + i;  dst = xh + i;
    } else {
        size_t r = i - XN;
        int w = (int)(r / WN);
        size_t o = r - (size_t)w * WN;
        src = (w == 0 ? Wq : w == 1 ? Wk : Wv) + o;
        dst = wh + (size_t)w * WN + o;
    }
    float4 v = *(const float4*)src;
    __half2* dp = (__half2*)dst;
    dp[0] = __floats2half2_rn(v.x, v.y);
    dp[1] = __floats2half2_rn(v.z, v.w);
}

// ===========================================================================
// Kernel 1: fused QKV GEMM (R15 config, unchanged).  4 warps, warp tile
// 64x64, CTA 128x128, BK=64, 2-stage cp.async, 2 CTAs/SM.
// ===========================================================================
#define GROW 144
#define GSTB (128 * GROW)
#define GEMM_SMEM_BYTES (4 * GSTB)        // 73728
#define CROW 136

__global__ __launch_bounds__(128, 2) void qkv_gemm_h(
    const float* __restrict__ bq, const float* __restrict__ bk,
    const float* __restrict__ bv)
{
    extern __shared__ __half sh[];
    const uint32_t sbase = smem_u32(sh);

    const int tid  = threadIdx.x;
    const int lane = tid & 31;
    const int wid  = tid >> 5;            // 0..3
    const int grp  = lane >> 2;
    const int qid  = lane & 3;
    const int wm   = (wid >> 1) * 64;
    const int wn   = (wid & 1) * 64;

    const int z  = blockIdx.z;
    const __half* X = g_Xh;
    const __half* W = g_Wh[z];
    const float* bias = (z == 0) ? bq : (z == 1) ? bk : bv;
    __half* out = (z == 0) ? g_Qh : (z == 1) ? g_Kh : g_Vh;
    const float scale = (z == 0) ? (0.125f * LOG2E) : 1.0f;

    const int m0 = blockIdx.y * 128;
    const int n0 = blockIdx.x * 128;

    const int lr = tid >> 3;              // 0..15, +16*rep
    const int lc = tid & 7;

    float acc[4][8][4];
    #pragma unroll
    for (int i = 0; i < 4; i++)
        #pragma unroll
        for (int j = 0; j < 8; j++)
            #pragma unroll
            for (int r = 0; r < 4; r++) acc[i][j][r] = 0.f;

    #define LOAD_STAGE(st, kb) do {                                           \
        _Pragma("unroll")                                                     \
        for (int rep = 0; rep < 8; rep++) {                                   \
            int r = lr + rep * 16;                                            \
            cpa16(sbase + (st) * GSTB + r * GROW + lc * 16,                   \
                  X + (size_t)(m0 + r) * HID + (kb) + lc * 8);                \
        }                                                                     \
        _Pragma("unroll")                                                     \
        for (int rep = 0; rep < 8; rep++) {                                   \
            int r = lr + rep * 16;                                            \
            cpa16(sbase + 2 * GSTB + (st) * GSTB + r * GROW + lc * 16,        \
                  W + (size_t)(n0 + r) * HID + (kb) + lc * 8);                \
        }                                                                     \
    } while (0)

    LOAD_STAGE(0, 0);
    CP_COMMIT();

    const uint32_t aoff = (wm + (lane & 15)) * GROW + (lane >> 4) * 16;
    const uint32_t boff = (wn + (lane & 7)) * GROW + (lane >> 3) * 16;

    for (int it = 0; it < HID / 64; it++) {
        CP_WAIT(0);
        __syncthreads();

        if (it + 1 < HID / 64) {
            LOAD_STAGE((it + 1) & 1, (it + 1) * 64);
            CP_COMMIT();
        }

        const int st = it & 1;
        const uint32_t Ab = sbase + st * GSTB + aoff;
        const uint32_t Bb = sbase + 2 * GSTB + st * GSTB + boff;

        #pragma unroll
        for (int s2 = 0; s2 < 2; s2++) {
            uint32_t bf[8][4];
            #pragma unroll
            for (int j = 0; j < 8; j++)
                ldsm_x4(bf[j], Bb + j * 8 * GROW + s2 * 64);
            #pragma unroll
            for (int s = 0; s < 2; s++) {
                uint32_t af[4][4];
                #pragma unroll
                for (int i = 0; i < 4; i++)
                    ldsm_x4(af[i], Ab + i * 16 * GROW + s2 * 64 + s * 32);
                #pragma unroll
                for (int j = 0; j < 8; j++)
                    #pragma unroll
                    for (int i = 0; i < 4; i++)
                        mma16(acc[i][j], af[i], bf[j][s * 2], bf[j][s * 2 + 1]);
            }
        }
    }

    // ---- epilogue: bias+scale -> C smem -> coalesced 128B stores ----
    float2 bias2[8];
    #pragma unroll
    for (int j = 0; j < 8; j++)
        bias2[j] = *(const float2*)&bias[n0 + wn + j * 8 + 2 * qid];

    __syncthreads();
    #pragma unroll
    for (int i = 0; i < 4; i++) {
        const int r0 = wm + i * 16 + grp;
        #pragma unroll
        for (int j = 0; j < 8; j++) {
            const int cc = wn + j * 8 + 2 * qid;
            *(__half2*)&sh[r0 * CROW + cc] = __floats2half2_rn(
                (acc[i][j][0] + bias2[j].x) * scale,
                (acc[i][j][1] + bias2[j].y) * scale);
            *(__half2*)&sh[(r0 + 8) * CROW + cc] = __floats2half2_rn(
                (acc[i][j][2] + bias2[j].x) * scale,
                (acc[i][j][3] + bias2[j].y) * scale);
        }
    }
    __syncthreads();

    #pragma unroll
    for (int p = 0; p < 16; p++) {
        const int u     = tid + p * 128;
        const int chunk = u & 7;
        const int half_ = (u >> 3) & 1;
        const int row   = u >> 4;
        const int m  = m0 + row;
        const int b_ = m >> 11;
        const int s  = m & 2047;
        const int h  = (n0 >> 6) + half_;
        uint4 v = *(const uint4*)&sh[row * CROW + half_ * 64 + chunk * 8];
        *(uint4*)&out[((size_t)(b_ * NH + h) * S_LEN + s) * HD + chunk * 8] = v;
    }
    #undef LOAD_STAGE
}

// ===========================================================================
// Kernel 2: flash attention (R15 base: 2-stage double buffer, 2 syncs/tile,
// mask pre-folded, staged coalesced output).
// NEW: mma chains software-pipelined — K/V fragments for 4 output columns
// preloaded, then ks-outer/j-inner issue order so each accumulator is
// revisited only every 8 mmas (covers HMMA latency).  Bit-identical math.
// ===========================================================================
#define AROW 144
#define ATILE (64 * AROW)                 // 9216 B
#define ABUF (2 * ATILE)                  // 18432 B
#define MSK_OFF_H ((2 * ABUF) / 2)        // half-index of mask buffer: 18432
#define ATT_SMEM_BYTES (2 * ABUF + 4096)  // 40960

__global__ __launch_bounds__(128, 2) void attention_h(
    const float* __restrict__ mask, float* __restrict__ out)
{
    extern __shared__ __half sh[];
    const uint32_t sbase = smem_u32(sh);

    const int tid  = threadIdx.x;
    const int lane = tid & 31;
    const int wid  = tid >> 5;            // 0..3
    const int grp  = lane >> 2;
    const int qid  = lane & 3;
    const int qb   = wid * 32;

    const int qt = blockIdx.x;            // 0..15
    const int bh = blockIdx.y;            // 0..63
    const int b_ = bh >> 4;
    const int h  = bh & 15;
    const int q0 = qt * 128;

    const __half* Kbh = g_Kh + (size_t)bh * S_LEN * HD;
    const __half* Vbh = g_Vh + (size_t)bh * S_LEN * HD;
    const float* mrow = mask + (size_t)b_ * S_LEN;

    // ---- pre-fold mask into smem: mh[k] = half(mask[k]*log2e - 4) ----
    for (int u = tid; u < 512; u += 128) {
        float4 mv = *(const float4*)&mrow[u * 4];
        *(__half2*)&sh[MSK_OFF_H + u * 4] =
            __floats2half2_rn(fmaf(mv.x, LOG2E, -4.f), fmaf(mv.y, LOG2E, -4.f));
        *(__half2*)&sh[MSK_OFF_H + u * 4 + 2] =
            __floats2half2_rn(fmaf(mv.z, LOG2E, -4.f), fmaf(mv.w, LOG2E, -4.f));
    }

    // ---- Q fragments (2 row-tiles of 16), register-resident ----
    uint32_t qf[2][4][4];
    {
        const __half* qp = g_Qh + ((size_t)bh * S_LEN + q0 + qb + grp) * HD + 2 * qid;
        #pragma unroll
        for (int i = 0; i < 2; i++) {
            const __half* qpi = qp + (size_t)i * 16 * HD;
            #pragma unroll
            for (int ks = 0; ks < 4; ks++) {
                qf[i][ks][0] = *(const uint32_t*)(qpi + ks * 16);
                qf[i][ks][1] = *(const uint32_t*)(qpi + 8 * HD + ks * 16);
                qf[i][ks][2] = *(const uint32_t*)(qpi + ks * 16 + 8);
                qf[i][ks][3] = *(const uint32_t*)(qpi + 8 * HD + ks * 16 + 8);
            }
        }
    }

    float o[2][8][4];
    #pragma unroll
    for (int i = 0; i < 2; i++)
        #pragma unroll
        for (int j = 0; j < 8; j++)
            #pragma unroll
            for (int r = 0; r < 4; r++) o[i][j][r] = 0.f;
    float l_[2][2] = {{0.f, 0.f}, {0.f, 0.f}};

    #define LOAD_TILE(buf, t) do {                                            \
        const int k0t_ = (t) * 64;                                            \
        _Pragma("unroll")                                                     \
        for (int rep = 0; rep < 8; rep++) {                                   \
            int u = tid + rep * 128;                                          \
            int tn = u >> 9, rr = (u >> 3) & 63, cc = u & 7;                  \
            const __half* g = tn                                              \
                ? (Vbh + (size_t)(k0t_ + rr) * HD + cc * 8)                   \
                : (Kbh + (size_t)(k0t_ + rr) * HD + cc * 8);                  \
            cpa16(sbase + (buf) * ABUF + tn * ATILE + rr * AROW + cc * 16, g);\
        }                                                                     \
    } while (0)

    LOAD_TILE(0, 0);
    CP_COMMIT();

    const uint32_t koff = (lane & 7) * AROW + (lane >> 3) * 16;       // x4
    const uint32_t voff = (lane & 15) * AROW + (lane >> 4) * 16;      // x4t

    for (int t = 0; t < S_LEN / 64; t++) {
        if (t + 1 < S_LEN / 64) LOAD_TILE((t + 1) & 1, t + 1);
        CP_COMMIT();
        CP_WAIT(1);
        __syncthreads();    // also orders the one-time mask fill before use

        const uint32_t Ksb = sbase + (t & 1) * ABUF;
        const uint32_t Vsb = Ksb + ATILE;

        // ---- S' = Q' K^T  (log2 domain), fp16 accum, pipelined chains ----
        uint32_t sacc[2][8][2];
        #pragma unroll
        for (int i = 0; i < 2; i++)
            #pragma unroll
            for (int j = 0; j < 8; j++) {
                sacc[i][j][0] = 0u;
                sacc[i][j][1] = 0u;
            }

        #pragma unroll
        for (int jg = 0; jg < 2; jg++) {
            // preload K fragments for 4 output columns x all 4 ks
            uint32_t kb[4][8];
            #pragma unroll
            for (int j = 0; j < 4; j++) {
                const uint32_t ka = Ksb + (jg * 4 + j) * 8 * AROW + koff;
                ldsm_x4(&kb[j][0], ka);        // ks 0,1
                ldsm_x4(&kb[j][4], ka + 64);   // ks 2,3
            }
            // ks-outer, j-inner: 8 independent chains, revisit gap = 8 mmas
            #pragma unroll
            for (int ks = 0; ks < 4; ks++)
                #pragma unroll
                for (int j = 0; j < 4; j++) {
                    mma16h(sacc[0][jg * 4 + j], qf[0][ks],
                           kb[j][2 * ks], kb[j][2 * ks + 1]);
                    mma16h(sacc[1][jg * 4 + j], qf[1][ks],
                           kb[j][2 * ks], kb[j][2 * ks + 1]);
                }
        }

        // ---- fixed-shift softmax: p = 2^(s' + mh) — all half2 ----
        const int k0t = t * 64;
        uint32_t pf[2][4][4];
        __half2 ps0[2], ps1[2];
        ps0[0] = ps0[1] = ps1[0] = ps1[1] = __float2half2_rn(0.f);
        #pragma unroll
        for (int j = 0; j < 8; j++) {
            const __half2 mh =
                *(const __half2*)&sh[MSK_OFF_H + k0t + j * 8 + 2 * qid];
            #pragma unroll
            for (int i = 0; i < 2; i++) {
                __half2 e0 = ex2h2(__hadd2(u2h(sacc[i][j][0]), mh));  // rows g
                __half2 e1 = ex2h2(__hadd2(u2h(sacc[i][j][1]), mh));  // rows g+8
                ps0[i] = __hadd2(ps0[i], e0);
                ps1[i] = __hadd2(ps1[i], e1);
                pf[i][j >> 1][(j & 1) * 2 + 0] = h2u(e0);
                pf[i][j >> 1][(j & 1) * 2 + 1] = h2u(e1);
            }
        }
        #pragma unroll
        for (int i = 0; i < 2; i++) {      // per-tile promote to fp32
            float2 f0 = __half22float2(ps0[i]);
            float2 f1 = __half22float2(ps1[i]);
            l_[i][0] += f0.x + f0.y;
            l_[i][1] += f1.x + f1.y;
        }

        // ---- O += P V  (fp32 accum), pipelined chains ----
        #pragma unroll
        for (int jg = 0; jg < 2; jg++) {
            // preload V^T fragments for 4 output columns x all 4 ks
            uint32_t vb[2][4][4];          // [jp-pair][ks][frag]
            #pragma unroll
            for (int pr = 0; pr < 2; pr++)
                #pragma unroll
                for (int ks = 0; ks < 4; ks++)
                    ldsm_x4t(vb[pr][ks],
                             Vsb + ks * 16 * AROW + (jg * 4 + pr * 2) * 16 + voff);
            // ks-outer: 8 independent chains, revisit gap = 8 mmas
            #pragma unroll
            for (int ks = 0; ks < 4; ks++)
                #pragma unroll
                for (int pr = 0; pr < 2; pr++) {
                    const int jp = jg * 4 + pr * 2;
                    mma16(o[0][jp],     pf[0][ks], vb[pr][ks][0], vb[pr][ks][1]);
                    mma16(o[0][jp + 1], pf[0][ks], vb[pr][ks][2], vb[pr][ks][3]);
                    mma16(o[1][jp],     pf[1][ks], vb[pr][ks][0], vb[pr][ks][1]);
                    mma16(o[1][jp + 1], pf[1][ks], vb[pr][ks][2], vb[pr][ks][3]);
                }
        }
        __syncthreads();
    }
    #undef LOAD_TILE

    // ---- final l reduction across the 4 qid lanes ----
    #pragma unroll
    for (int i = 0; i < 2; i++)
        #pragma unroll
        for (int g2 = 0; g2 < 2; g2++)
            #pragma unroll
            for (int off = 1; off < 4; off <<= 1)
                l_[i][g2] += __shfl_xor_sync(0xFFFFFFFF, l_[i][g2], off);

    // ---- normalize -> stage C in smem (row stride 72 f32) -> coalesced ----
    float* cs = (float*)sh;               // K/V buffers are dead now
    __syncthreads();                      // all warps done with smem tiles
    #pragma unroll
    for (int i = 0; i < 2; i++) {
        const float i0 = 1.0f / l_[i][0];
        const float i1 = 1.0f / l_[i][1];
        const int r0 = qb + i * 16 + grp;
        #pragma unroll
        for (int j = 0; j < 8; j++) {
            const int dd = j * 8 + 2 * qid;
            *(float2*)&cs[r0 * 72 + dd] =
                make_float2(o[i][j][0] * i0, o[i][j][1] * i0);
            *(float2*)&cs[(r0 + 8) * 72 + dd] =
                make_float2(o[i][j][2] * i1, o[i][j][3] * i1);
        }
    }
    __syncthreads();

    #pragma unroll
    for (int p = 0; p < 16; p++) {
        const int u   = tid + p * 128;
        const int c4  = u & 15;            // 16 float4 per 64-float row
        const int row = u >> 4;            // 0..127
        const int s   = q0 + row;
        float4 v = *(const float4*)&cs[row * 72 + c4 * 4];
        *(float4*)&out[((size_t)(b_ * S_LEN + s)) * HID + h * HD + c4 * 4] = v;
    }
}

// ===========================================================================
extern "C" void kernel_launch(void* const* d_in, const int* in_sizes, int n_in,
                              void* d_out, int out_size)
{
    const float* X    = (const float*)d_in[0];
    const float* mask = (const float*)d_in[1];
    const float* Wq   = (const float*)d_in[2];
    const float* bq   = (const float*)d_in[3];
    const float* Wk   = (const float*)d_in[4];
    const float* bk   = (const float*)d_in[5];
    const float* Wv   = (const float*)d_in[6];
    const float* bv   = (const float*)d_in[7];
    float* out = (float*)d_out;

    cudaFuncSetAttribute(qkv_gemm_h,
        cudaFuncAttributeMaxDynamicSharedMemorySize, GEMM_SMEM_BYTES);

    __half* xh;  cudaGetSymbolAddress((void**)&xh, g_Xh);
    __half* wh;  cudaGetSymbolAddress((void**)&wh, g_Wh);

    // prepass: fp32 -> fp16
    cvt_all<<<CVT_BLOCKS, 256>>>(X, Wq, Wk, Wv, xh, wh);

    // QKV projection (R13/R15 config)
    dim3 g1(HID / 128, M_TOTAL / 128, 3);   // (8, 64, 3)
    qkv_gemm_h<<<g1, 128, GEMM_SMEM_BYTES>>>(bq, bk, bv);

    // attention
    dim3 g2(S_LEN / 128, NBH);              // (16, 64)
    attention_h<<<g2, 128, ATT_SMEM_BYTES>>>(mask, out);
}